// round 7
// baseline (speedup 1.0000x reference)
#include <cuda_runtime.h>
#include <cuda_fp16.h>
#include <cstdint>

// VectorQuantStraightThrough via warp-level HMMA (mma.sync m16n8k16 fp16),
// fp32-emulated dot with fp16 2-way splits, 3 cross terms.
//   z scaled 2^3, e scaled 2^15 => accum = 2^18*dot; 2*dot = accum*2^-17 exact.
//   d2 = fl( fl(z2 - 2dot) + e2 )  (reference fp32 rounding replicated).
// Round 7: single fused kernel, 512 threads (16 warps: 8 M-slices x 2 N-halves),
// in-CTA emb->split conversion. All numeric orders identical to passing r5/r6.

#define NROWS (32 * 4096)   // 131072
#define DDIM  64
#define KCB   512
#define MT    128           // rows per CTA
#define NTILES (NROWS / MT) // 1024 CTAs
#define TPB   512

// smem byte offsets (rows padded to 72 halves = 144 B)
#define SM_B0   0           // e-split0 [512][72] half
#define SM_B1   73728       // e-split1 [512][72] half
#define SM_A0   147456      // z-split0 [128][72] half   (also emb-staging scratch)
#define SM_A1   165888      // z-split1 [128][72] half
#define SM_Z32  184320      // z tile fp32 [128][64]
#define SM_SCR  SM_A0       // fp32 staging scratch (64 KB needed; 69.6 KB here)
#define SM_E2   217088      // e2 [512] float
#define SM_Z2   219136      // z2 [128] float
#define SM_VAL0 219648      // best val (N-half 0) [128] float
#define SM_VAL1 220160
#define SM_IDX0 220672      // best idx [128] int
#define SM_IDX1 221184
#define SM_TOTAL 221696

#define TWO_DOT_SCALE (1.0f / 131072.0f)   // 2^-17

__device__ __forceinline__ void mma16816(float* c, const uint32_t* a,
                                         const uint32_t* b) {
    asm volatile(
        "mma.sync.aligned.m16n8k16.row.col.f32.f16.f16.f32 "
        "{%0,%1,%2,%3}, {%4,%5,%6,%7}, {%8,%9}, {%0,%1,%2,%3};"
        : "+f"(c[0]), "+f"(c[1]), "+f"(c[2]), "+f"(c[3])
        : "r"(a[0]), "r"(a[1]), "r"(a[2]), "r"(a[3]), "r"(b[0]), "r"(b[1]));
}

__global__ __launch_bounds__(TPB, 1)
void vq_main_kernel(const float* __restrict__ z,
                    const float* __restrict__ emb,
                    float* __restrict__ out,
                    long long out_size) {
    extern __shared__ char smem[];
    const int tid = threadIdx.x;
    const int w   = tid >> 5;
    const int l   = tid & 31;
    const int tile = blockIdx.x;

    float* e2s_w = (float*)(smem + SM_E2);

    // ---- Phase 1: emb -> fp16 splits + e2, two 256-code halves ----
    #pragma unroll 1
    for (int half = 0; half < 2; half++) {
        // stage 256 codes fp32 coalesced into scratch
        {
            const float4* src = (const float4*)(emb + (size_t)half * 256 * DDIM);
            float4* dst = (float4*)(smem + SM_SCR);
            #pragma unroll
            for (int i = tid; i < 256 * DDIM / 4; i += TPB) dst[i] = src[i];
        }
        __syncthreads();
        const float* ef = (const float*)(smem + SM_SCR);
        // splits (scaled 2^15), padded B layout
        #pragma unroll
        for (int e = tid; e < 256 * DDIM; e += TPB) {
            const int row = e >> 6, kk = e & 63;
            const float sv = ef[e] * 32768.0f;   // exact
            const __half h0 = __float2half_rn(sv);
            const float  r  = sv - __half2float(h0);
            const __half h1 = __float2half_rn(r);
            const int gr = half * 256 + row;
            *(__half*)(smem + SM_B0 + gr * 144 + kk * 2) = h0;
            *(__half*)(smem + SM_B1 + gr * 144 + kk * 2) = h1;
        }
        // e2: one code per thread, exact sequential fmaf chain (as r5/r6)
        if (tid < 256) {
            const float* ecode = ef + tid * DDIM;
            float s = 0.f;
            #pragma unroll 8
            for (int d = 0; d < DDIM; d++) s = fmaf(ecode[d], ecode[d], s);
            e2s_w[half * 256 + tid] = s;
        }
        __syncthreads();   // scratch free for next half / z
    }

    // ---- Phase 2: z tile ----
    {
        const float4* src = (const float4*)(z + (size_t)tile * MT * DDIM);
        float4* dst = (float4*)(smem + SM_Z32);
        #pragma unroll
        for (int i = tid; i < MT * DDIM / 4; i += TPB) dst[i] = src[i];
    }
    __syncthreads();
    {   // z splits (scaled 2^3), padded A layout
        const float* z32 = (const float*)(smem + SM_Z32);
        #pragma unroll
        for (int e = tid; e < MT * DDIM; e += TPB) {
            const int row = e >> 6, kk = e & 63;
            const float sv = z32[e] * 8.0f;      // exact
            const __half h0 = __float2half_rn(sv);
            const float  r  = sv - __half2float(h0);
            const __half h1 = __float2half_rn(r);
            *(__half*)(smem + SM_A0 + row * 144 + kk * 2) = h0;
            *(__half*)(smem + SM_A1 + row * 144 + kk * 2) = h1;
        }
    }
    // z2 per row: EXACT round-2/5/6 evaluation order
    if (tid < MT) {
        const float* zr = (const float*)(smem + SM_Z32) + tid * DDIM;
        float c[8];
        #pragma unroll
        for (int p = 0; p < 8; p++) {
            float s = 0.f;
            #pragma unroll
            for (int j = 0; j < 8; j++) s = fmaf(zr[p + 8 * j], zr[p + 8 * j], s);
            c[p] = s;
        }
        const float lo = __fadd_rn(__fadd_rn(c[0], c[2]), __fadd_rn(c[4], c[6]));
        const float hi = __fadd_rn(__fadd_rn(c[1], c[3]), __fadd_rn(c[5], c[7]));
        ((float*)(smem + SM_Z2))[tid] = __fadd_rn(lo, hi);
    }
    __syncthreads();

    // ---- warp partition: 8 M-slices (16 rows) x 2 N-halves ----
    const int mrow0 = (w & 7) * 16;
    const int nhalf = w >> 3;              // 0 or 1
    const int ncol0 = nhalf * 256;
    const int lr = l >> 2;                 // 0..7
    const int kb = (l & 3) * 2;            // 0,2,4,6

    // A fragments in regs: [split][ktile][4]
    uint32_t Af[2][4][4];
    {
        const int r0 = mrow0 + lr;
        #pragma unroll
        for (int s = 0; s < 2; s++) {
            const char* Ab = smem + (s ? SM_A1 : SM_A0);
            #pragma unroll
            for (int kt = 0; kt < 4; kt++) {
                const int k0 = kt * 16 + kb;
                Af[s][kt][0] = *(const uint32_t*)(Ab + r0 * 144 + k0 * 2);
                Af[s][kt][1] = *(const uint32_t*)(Ab + (r0 + 8) * 144 + k0 * 2);
                Af[s][kt][2] = *(const uint32_t*)(Ab + r0 * 144 + (k0 + 8) * 2);
                Af[s][kt][3] = *(const uint32_t*)(Ab + (r0 + 8) * 144 + (k0 + 8) * 2);
            }
        }
    }

    const float* z2s = (const float*)(smem + SM_Z2);
    const float* e2s = (const float*)(smem + SM_E2);
    const float z2a = z2s[mrow0 + lr];
    const float z2b = z2s[mrow0 + lr + 8];

    float bv[2] = {3.4e38f, 3.4e38f};
    int   bi[2] = {0, 0};

    // ---- main loop: 32 n-tiles ----
    for (int j = 0; j < 32; j++) {
        const int col0 = ncol0 + j * 8;
        const int nr = col0 + lr;

        uint32_t Bf[2][4][2];
        #pragma unroll
        for (int s = 0; s < 2; s++) {
            const char* Bb = smem + (s ? SM_B1 : SM_B0);
            #pragma unroll
            for (int kt = 0; kt < 4; kt++) {
                const int k0 = kt * 16 + kb;
                Bf[s][kt][0] = *(const uint32_t*)(Bb + nr * 144 + k0 * 2);
                Bf[s][kt][1] = *(const uint32_t*)(Bb + nr * 144 + (k0 + 8) * 2);
            }
        }

        float C01[4] = {0.f, 0.f, 0.f, 0.f};   // a0*b1
        float C10[4] = {0.f, 0.f, 0.f, 0.f};   // a1*b0
        float C00[4] = {0.f, 0.f, 0.f, 0.f};   // a0*b0
        #pragma unroll
        for (int kt = 0; kt < 4; kt++) {
            mma16816(C01, Af[0][kt], Bf[1][kt]);
            mma16816(C10, Af[1][kt], Bf[0][kt]);
            mma16816(C00, Af[0][kt], Bf[0][kt]);
        }

        // combine small-first, reference rounding, running argmin
        const int ca = col0 + kb;
        const float e2a = e2s[ca], e2b = e2s[ca + 1];
        float td[4];
        #pragma unroll
        for (int q = 0; q < 4; q++) {
            const float s = __fadd_rn(__fadd_rn(C01[q], C10[q]), C00[q]);
            td[q] = __fmul_rn(s, TWO_DOT_SCALE);
        }
        const float d00 = __fadd_rn(__fsub_rn(z2a, td[0]), e2a);
        const float d01 = __fadd_rn(__fsub_rn(z2a, td[1]), e2b);
        const float d10 = __fadd_rn(__fsub_rn(z2b, td[2]), e2a);
        const float d11 = __fadd_rn(__fsub_rn(z2b, td[3]), e2b);
        if (d00 < bv[0]) { bv[0] = d00; bi[0] = ca; }
        if (d01 < bv[0]) { bv[0] = d01; bi[0] = ca + 1; }
        if (d10 < bv[1]) { bv[1] = d10; bi[1] = ca; }
        if (d11 < bv[1]) { bv[1] = d11; bi[1] = ca + 1; }
    }

    // ---- quad reduce (min, lowest index on tie), write per-row partials ----
    #pragma unroll
    for (int h = 0; h < 2; h++) {
        float v = bv[h];
        int   i = bi[h];
        #pragma unroll
        for (int s = 1; s <= 2; s <<= 1) {
            const float ov = __shfl_xor_sync(0xFFFFFFFFu, v, s);
            const int   oi = __shfl_xor_sync(0xFFFFFFFFu, i, s);
            if (ov < v || (ov == v && oi < i)) { v = ov; i = oi; }
        }
        if ((l & 3) == 0) {
            const int row = mrow0 + lr + h * 8;
            ((float*)(smem + (nhalf ? SM_VAL1 : SM_VAL0)))[row] = v;
            ((int*)  (smem + (nhalf ? SM_IDX1 : SM_IDX0)))[row] = i;
        }
    }
    __syncthreads();

    // ---- output: merge N-halves, gather emb fp32, write ----
    if (tid < 256) {
        const float* v0s = (const float*)(smem + SM_VAL0);
        const float* v1s = (const float*)(smem + SM_VAL1);
        const int*   i0s = (const int*)(smem + SM_IDX0);
        const int*   i1s = (const int*)(smem + SM_IDX1);

        const int r  = tid >> 1;            // local row 0..127
        const int hh = tid & 1;             // half of the 64 dims
        const int idx = (v1s[r] < v0s[r]) ? i1s[r] : i0s[r];  // half0 wins ties

        const long long n   = (long long)tile * MT + r;
        const long long ND  = (long long)NROWS * DDIM;   // 8388608
        const float4* ev = (const float4*)(emb + (long long)idx * DDIM) + hh * 8;
        const long long off = n * DDIM + hh * 32;

        if (out_size >= ND) {
            float4* o = (float4*)(out + off);
            #pragma unroll
            for (int q = 0; q < 8; q++) o[q] = ev[q];
        }
        if (out_size >= 2 * ND) {
            float4* o = (float4*)(out + ND + off);
            #pragma unroll
            for (int q = 0; q < 8; q++) o[q] = ev[q];
        }
        if (hh == 0) {   // indices as float (0..511 exact)
            if (out_size >= 2 * ND + NROWS)      out[2 * ND + n] = (float)idx;
            else if (out_size == ND + NROWS)     out[ND + n]     = (float)idx;
            else if (out_size == NROWS)          out[n]          = (float)idx;
        }
    }
}

// ---------------------------------------------------------------------------
extern "C" void kernel_launch(void* const* d_in, const int* in_sizes, int n_in,
                              void* d_out, int out_size) {
    const float* z   = (const float*)d_in[0];
    const float* emb = (const float*)d_in[1];
    if (n_in >= 2 && in_sizes[0] == KCB * DDIM && in_sizes[1] == NROWS * DDIM) {
        z   = (const float*)d_in[1];
        emb = (const float*)d_in[0];
    }

    static int configured = -1;
    if (configured < 0) {
        cudaFuncSetAttribute(vq_main_kernel,
                             cudaFuncAttributeMaxDynamicSharedMemorySize, SM_TOTAL);
        configured = 1;
    }

    vq_main_kernel<<<NTILES, TPB, SM_TOTAL>>>(z, emb, (float*)d_out,
                                              (long long)out_size);
}

// round 9
// speedup vs baseline: 2.0881x; 2.0881x over previous
#include <cuda_runtime.h>
#include <cuda_fp16.h>
#include <cstdint>

// VectorQuantStraightThrough via warp-level HMMA (mma.sync m16n8k16 fp16),
// fp32-emulated dot with fp16 2-way splits, 3 cross terms.
//   z scaled 2^3, e scaled 2^15 => accum = 2^18*dot; 2*dot = accum*2^-17 exact.
//   d2 = fl( fl(z2 - 2dot) + e2 )  (reference fp32 rounding replicated).
// Round 8: persistent main kernel (B staged once per CTA), packed f16 pair
// conversions for z splits, double-buffered B fragments. Numeric orders
// identical to passing rounds 5/6.

#define NROWS (32 * 4096)   // 131072
#define DDIM  64
#define KCB   512
#define MT    128           // rows per tile
#define NTILES (NROWS / MT) // 1024 tiles
#define GRID_MAIN 148       // persistent
#define TPB   256

// smem byte offsets (rows padded to 72 halves = 144 B)
#define SM_B0   0           // e-split0 [512][72] half
#define SM_B1   73728       // e-split1
#define SM_A0   147456      // z-split0 [128][72] half
#define SM_A1   165888      // z-split1
#define SM_Z32  184320      // z tile fp32 [128][64]
#define SM_E2   217088      // e2 [512] float
#define SM_Z2   219136      // z2 [128] float
#define SM_VAL0 219648      // best val (N-half 0) [128] float
#define SM_VAL1 220160
#define SM_IDX0 220672      // best idx [128] int
#define SM_IDX1 221184
#define SM_TOTAL 221696

#define TWO_DOT_SCALE (1.0f / 131072.0f)   // 2^-17

// ---- device scratch ----
__device__ __half g_b0[KCB * DDIM];
__device__ __half g_b1[KCB * DDIM];
__device__ float  g_e2[KCB];

__device__ __forceinline__ void mma16816(float* c, const uint32_t* a,
                                         const uint32_t* b) {
    asm volatile(
        "mma.sync.aligned.m16n8k16.row.col.f32.f16.f16.f32 "
        "{%0,%1,%2,%3}, {%4,%5,%6,%7}, {%8,%9}, {%0,%1,%2,%3};"
        : "+f"(c[0]), "+f"(c[1]), "+f"(c[2]), "+f"(c[3])
        : "r"(a[0]), "r"(a[1]), "r"(a[2]), "r"(a[3]), "r"(b[0]), "r"(b[1]));
}

// ---------------- prep: e-splits (scaled 2^15) + ||e||^2 (as round 6) -----
__global__ __launch_bounds__(128, 1)
void vq_prep_kernel(const float* __restrict__ emb) {
    __shared__ float se[128 * DDIM];   // 32 KB
    const int tid = threadIdx.x;
    const int k0  = blockIdx.x * 128;

    const float4* src = (const float4*)(emb + (size_t)k0 * DDIM);
    float4* dst = (float4*)se;
    #pragma unroll
    for (int i = tid; i < 128 * DDIM / 4; i += 128) dst[i] = src[i];
    __syncthreads();

    const int k = k0 + tid;
    const float* e = se + tid * DDIM;
    float s = 0.f;
    #pragma unroll 8
    for (int d = 0; d < DDIM; d++) {
        const float v = e[d];
        s = fmaf(v, v, s);                     // exact round-2/5 e2 chain order
        const float sv = v * 32768.0f;         // exact
        const __half h0 = __float2half_rn(sv);
        const float  r  = sv - __half2float(h0);
        const __half h1 = __float2half_rn(r);
        g_b0[k * DDIM + d] = h0;
        g_b1[k * DDIM + d] = h1;
    }
    g_e2[k] = s;
}

// ---------------- main persistent kernel ----------------------------------
__global__ __launch_bounds__(TPB, 1)
void vq_main_kernel(const float* __restrict__ z,
                    const float* __restrict__ emb,
                    float* __restrict__ out,
                    long long out_size) {
    extern __shared__ char smem[];
    const int tid = threadIdx.x;
    const int w   = tid >> 5;
    const int l   = tid & 31;

    // ---- one-time prologue: stage e-splits (padded) + e2 ----
    {
        const uint4* s0 = (const uint4*)g_b0;
        const uint4* s1 = (const uint4*)g_b1;
        #pragma unroll
        for (int c = tid; c < KCB * DDIM / 8; c += TPB) {   // 4096 chunks
            const int row = c >> 3, cc = c & 7;
            *(uint4*)(smem + SM_B0 + row * 144 + cc * 16) = s0[c];
            *(uint4*)(smem + SM_B1 + row * 144 + cc * 16) = s1[c];
        }
        #pragma unroll
        for (int i = tid; i < KCB; i += TPB)
            ((float*)(smem + SM_E2))[i] = g_e2[i];
    }

    // warp partition: 4 M-slices x 2 N-halves (as rounds 5/6)
    const int mrow0 = (w & 3) * 32;
    const int nhalf = w >> 2;
    const int ncol0 = nhalf * 256;
    const int lr = l >> 2;
    const int kb = (l & 3) * 2;

    const float* z2s = (const float*)(smem + SM_Z2);
    const float* e2s = (const float*)(smem + SM_E2);

    // ---- persistent tile loop ----
    for (int tile = blockIdx.x; tile < NTILES; tile += GRID_MAIN) {
        __syncthreads();   // protect SM_Z32 / A-splits / VAL/IDX reuse

        // stage z tile fp32 (coalesced)
        {
            const float4* src = (const float4*)(z + (size_t)tile * MT * DDIM);
            float4* dst = (float4*)(smem + SM_Z32);
            #pragma unroll
            for (int i = tid; i < MT * DDIM / 4; i += TPB) dst[i] = src[i];
        }
        __syncthreads();

        // convert z -> fp16 splits (scaled 2^3), packed pair conversions.
        // Per-element results identical to __float2half_rn (RN per lane).
        {
            const float* z32 = (const float*)(smem + SM_Z32);
            #pragma unroll
            for (int e2i = tid; e2i < MT * DDIM / 2; e2i += TPB) {
                const int e = e2i * 2;
                const int row = e >> 6, kk = e & 63;
                const float2 vv = *(const float2*)(z32 + e);
                const float2 sv = make_float2(vv.x * 8.0f, vv.y * 8.0f);
                const __half2 h0 = __float22half2_rn(sv);
                const float2 b = __half22float2(h0);
                const float2 r = make_float2(sv.x - b.x, sv.y - b.y);
                const __half2 h1 = __float22half2_rn(r);
                *(__half2*)(smem + SM_A0 + row * 144 + kk * 2) = h0;
                *(__half2*)(smem + SM_A1 + row * 144 + kk * 2) = h1;
            }
        }
        // z2 per row: EXACT round-2/5/6 evaluation order
        if (tid < MT) {
            const float* zr = (const float*)(smem + SM_Z32) + tid * DDIM;
            float c[8];
            #pragma unroll
            for (int p = 0; p < 8; p++) {
                float s = 0.f;
                #pragma unroll
                for (int j = 0; j < 8; j++) s = fmaf(zr[p + 8 * j], zr[p + 8 * j], s);
                c[p] = s;
            }
            const float lo = __fadd_rn(__fadd_rn(c[0], c[2]), __fadd_rn(c[4], c[6]));
            const float hi = __fadd_rn(__fadd_rn(c[1], c[3]), __fadd_rn(c[5], c[7]));
            ((float*)(smem + SM_Z2))[tid] = __fadd_rn(lo, hi);
        }
        __syncthreads();

        // A fragments in regs: [msub][split][ktile][4]
        uint32_t Af[2][2][4][4];
        #pragma unroll
        for (int m = 0; m < 2; m++) {
            const int r0 = mrow0 + m * 16 + lr;
            #pragma unroll
            for (int s = 0; s < 2; s++) {
                const char* Ab = smem + (s ? SM_A1 : SM_A0);
                #pragma unroll
                for (int kt = 0; kt < 4; kt++) {
                    const int k0 = kt * 16 + kb;
                    Af[m][s][kt][0] = *(const uint32_t*)(Ab + r0 * 144 + k0 * 2);
                    Af[m][s][kt][1] = *(const uint32_t*)(Ab + (r0 + 8) * 144 + k0 * 2);
                    Af[m][s][kt][2] = *(const uint32_t*)(Ab + r0 * 144 + (k0 + 8) * 2);
                    Af[m][s][kt][3] = *(const uint32_t*)(Ab + (r0 + 8) * 144 + (k0 + 8) * 2);
                }
            }
        }

        float z2v[2][2];
        #pragma unroll
        for (int m = 0; m < 2; m++) {
            z2v[m][0] = z2s[mrow0 + m * 16 + lr];
            z2v[m][1] = z2s[mrow0 + m * 16 + lr + 8];
        }

        float bv[2][2] = {{3.4e38f, 3.4e38f}, {3.4e38f, 3.4e38f}};
        int   bi[2][2] = {{0, 0}, {0, 0}};

        // B-fragment loader
        auto loadB = [&](uint32_t (&Bf)[2][4][2], int j) {
            const int nr = ncol0 + j * 8 + lr;
            #pragma unroll
            for (int s = 0; s < 2; s++) {
                const char* Bb = smem + (s ? SM_B1 : SM_B0);
                #pragma unroll
                for (int kt = 0; kt < 4; kt++) {
                    const int k0 = kt * 16 + kb;
                    Bf[s][kt][0] = *(const uint32_t*)(Bb + nr * 144 + k0 * 2);
                    Bf[s][kt][1] = *(const uint32_t*)(Bb + nr * 144 + (k0 + 8) * 2);
                }
            }
        };

        uint32_t Bbuf[2][2][4][2];
        loadB(Bbuf[0], 0);

        // ---- main loop: 32 n-tiles, double-buffered B ----
        #pragma unroll 2
        for (int j = 0; j < 32; j++) {
            const int cur = j & 1;
            if (j < 31) loadB(Bbuf[cur ^ 1], j + 1);

            float C01[2][4] = {{0.f,0.f,0.f,0.f},{0.f,0.f,0.f,0.f}};  // a0*b1
            float C10[2][4] = {{0.f,0.f,0.f,0.f},{0.f,0.f,0.f,0.f}};  // a1*b0
            float C00[2][4] = {{0.f,0.f,0.f,0.f},{0.f,0.f,0.f,0.f}};  // a0*b0
            #pragma unroll
            for (int kt = 0; kt < 4; kt++) {
                mma16816(C01[0], Af[0][0][kt], Bbuf[cur][1][kt]);
                mma16816(C01[1], Af[1][0][kt], Bbuf[cur][1][kt]);
                mma16816(C10[0], Af[0][1][kt], Bbuf[cur][0][kt]);
                mma16816(C10[1], Af[1][1][kt], Bbuf[cur][0][kt]);
                mma16816(C00[0], Af[0][0][kt], Bbuf[cur][0][kt]);
                mma16816(C00[1], Af[1][0][kt], Bbuf[cur][0][kt]);
            }

            const int ca = ncol0 + j * 8 + kb;
            const float e2a = e2s[ca], e2b = e2s[ca + 1];
            #pragma unroll
            for (int m = 0; m < 2; m++) {
                float td[4];
                #pragma unroll
                for (int q = 0; q < 4; q++) {
                    const float s = __fadd_rn(__fadd_rn(C01[m][q], C10[m][q]),
                                              C00[m][q]);
                    td[q] = __fmul_rn(s, TWO_DOT_SCALE);
                }
                const float d00 = __fadd_rn(__fsub_rn(z2v[m][0], td[0]), e2a);
                const float d01 = __fadd_rn(__fsub_rn(z2v[m][0], td[1]), e2b);
                const float d10 = __fadd_rn(__fsub_rn(z2v[m][1], td[2]), e2a);
                const float d11 = __fadd_rn(__fsub_rn(z2v[m][1], td[3]), e2b);
                if (d00 < bv[m][0]) { bv[m][0] = d00; bi[m][0] = ca; }
                if (d01 < bv[m][0]) { bv[m][0] = d01; bi[m][0] = ca + 1; }
                if (d10 < bv[m][1]) { bv[m][1] = d10; bi[m][1] = ca; }
                if (d11 < bv[m][1]) { bv[m][1] = d11; bi[m][1] = ca + 1; }
            }
        }

        // quad reduce (min, lowest index on tie), write per-row partials
        #pragma unroll
        for (int m = 0; m < 2; m++) {
            #pragma unroll
            for (int h = 0; h < 2; h++) {
                float v = bv[m][h];
                int   i = bi[m][h];
                #pragma unroll
                for (int s = 1; s <= 2; s <<= 1) {
                    const float ov = __shfl_xor_sync(0xFFFFFFFFu, v, s);
                    const int   oi = __shfl_xor_sync(0xFFFFFFFFu, i, s);
                    if (ov < v || (ov == v && oi < i)) { v = ov; i = oi; }
                }
                if ((l & 3) == 0) {
                    const int row = mrow0 + m * 16 + lr + h * 8;
                    ((float*)(smem + (nhalf ? SM_VAL1 : SM_VAL0)))[row] = v;
                    ((int*)  (smem + (nhalf ? SM_IDX1 : SM_IDX0)))[row] = i;
                }
            }
        }
        __syncthreads();

        // output: merge N-halves, gather emb fp32, write
        {
            const float* v0s = (const float*)(smem + SM_VAL0);
            const float* v1s = (const float*)(smem + SM_VAL1);
            const int*   i0s = (const int*)(smem + SM_IDX0);
            const int*   i1s = (const int*)(smem + SM_IDX1);

            const int r  = tid >> 1;            // local row 0..127
            const int hh = tid & 1;             // half of the 64 dims
            const int idx = (v1s[r] < v0s[r]) ? i1s[r] : i0s[r];  // half0 wins ties

            const long long n   = (long long)tile * MT + r;
            const long long ND  = (long long)NROWS * DDIM;   // 8388608
            const float4* ev = (const float4*)(emb + (long long)idx * DDIM) + hh * 8;
            const long long off = n * DDIM + hh * 32;

            if (out_size >= ND) {
                float4* o = (float4*)(out + off);
                #pragma unroll
                for (int q = 0; q < 8; q++) o[q] = ev[q];
            }
            if (out_size >= 2 * ND) {
                float4* o = (float4*)(out + ND + off);
                #pragma unroll
                for (int q = 0; q < 8; q++) o[q] = ev[q];
            }
            if (hh == 0) {   // indices as float (0..511 exact)
                if (out_size >= 2 * ND + NROWS)      out[2 * ND + n] = (float)idx;
                else if (out_size == ND + NROWS)     out[ND + n]     = (float)idx;
                else if (out_size == NROWS)          out[n]          = (float)idx;
            }
        }
    }
}

// ---------------------------------------------------------------------------
extern "C" void kernel_launch(void* const* d_in, const int* in_sizes, int n_in,
                              void* d_out, int out_size) {
    const float* z   = (const float*)d_in[0];
    const float* emb = (const float*)d_in[1];
    if (n_in >= 2 && in_sizes[0] == KCB * DDIM && in_sizes[1] == NROWS * DDIM) {
        z   = (const float*)d_in[1];
        emb = (const float*)d_in[0];
    }

    static int configured = -1;
    if (configured < 0) {
        cudaFuncSetAttribute(vq_main_kernel,
                             cudaFuncAttributeMaxDynamicSharedMemorySize, SM_TOTAL);
        configured = 1;
    }

    vq_prep_kernel<<<4, 128>>>(emb);
    vq_main_kernel<<<GRID_MAIN, TPB, SM_TOTAL>>>(z, emb, (float*)d_out,
                                                 (long long)out_size);
}

// round 10
// speedup vs baseline: 2.5013x; 1.1978x over previous
#include <cuda_runtime.h>
#include <cuda_fp16.h>
#include <cstdint>

// VectorQuantStraightThrough via warp-level HMMA (mma.sync m16n8k16 fp16),
// fp32-emulated dot with fp16 2-way splits, 3 cross terms.
//   z scaled 2^3, e scaled 2^15 => accum = 2^18*dot; 2*dot = accum*2^-17 exact.
//   d2 = fl( fl(z2 - 2dot) + e2 )  (reference fp32 rounding replicated).
// Round 10: k-split (256 codes/CTA) + swizzled unpadded smem + <=128 regs
// => 2 CTAs/SM (4 warps/SMSP). Partial argmin to global; merge kernel wraps up.

#define NROWS (32 * 4096)   // 131072
#define DDIM  64
#define KCB   512
#define KHALF 256
#define MT    128           // rows per tile
#define NTILES (NROWS / MT) // 1024 tiles
#define GRID_MAIN (148 * 2) // persistent, 2 CTAs/SM
#define TPB   256

// smem byte offsets (unpadded 128B rows, XOR-swizzled)
#define SM_B0   0           // e-split0 [256][64] half   32768 B
#define SM_B1   32768       // e-split1                  32768 B
#define SM_A0   65536       // z-split0 [128][64] half   16384 B
#define SM_A1   81920       // z-split1                  16384 B
#define SM_E2   98304       // e2 half [256] float        1024 B
#define SM_Z2   99328       // z2 [128] float              512 B
#define SM_TOTAL 99840

#define TWO_DOT_SCALE (1.0f / 131072.0f)   // 2^-17
#define SWZ(x) ((x) ^ ((((x) >> 7) & 7) << 4))

// ---- device scratch ----
__device__ __align__(16) __half g_b0[KCB * DDIM];
__device__ __align__(16) __half g_b1[KCB * DDIM];
__device__ float  g_e2[KCB];
__device__ float2 g_part[2][NROWS];   // (best_d, best_global_idx as float)

__device__ __forceinline__ void mma16816(float* c, const uint32_t* a,
                                         const uint32_t* b) {
    asm volatile(
        "mma.sync.aligned.m16n8k16.row.col.f32.f16.f16.f32 "
        "{%0,%1,%2,%3}, {%4,%5,%6,%7}, {%8,%9}, {%0,%1,%2,%3};"
        : "+f"(c[0]), "+f"(c[1]), "+f"(c[2]), "+f"(c[3])
        : "r"(a[0]), "r"(a[1]), "r"(a[2]), "r"(a[3]), "r"(b[0]), "r"(b[1]));
}

// ---------------- prep: e-splits (scaled 2^15) + ||e||^2 (unchanged) ------
__global__ __launch_bounds__(128, 1)
void vq_prep_kernel(const float* __restrict__ emb) {
    __shared__ float se[128 * DDIM];   // 32 KB
    const int tid = threadIdx.x;
    const int k0  = blockIdx.x * 128;

    const float4* src = (const float4*)(emb + (size_t)k0 * DDIM);
    float4* dst = (float4*)se;
    #pragma unroll
    for (int i = tid; i < 128 * DDIM / 4; i += 128) dst[i] = src[i];
    __syncthreads();

    const int k = k0 + tid;
    const float* e = se + tid * DDIM;
    float s = 0.f;
    #pragma unroll 8
    for (int d = 0; d < DDIM; d++) {
        const float v = e[d];
        s = fmaf(v, v, s);                     // exact passing e2 chain order
        const float sv = v * 32768.0f;         // exact
        const __half h0 = __float2half_rn(sv);
        const float  r  = sv - __half2float(h0);
        const __half h1 = __float2half_rn(r);
        g_b0[k * DDIM + d] = h0;
        g_b1[k * DDIM + d] = h1;
    }
    g_e2[k] = s;
}

// ---------------- main persistent kernel (one codebook half per CTA) ------
__global__ __launch_bounds__(TPB, 2)
void vq_main_kernel(const float* __restrict__ z) {
    extern __shared__ char smem[];
    const int tid  = threadIdx.x;
    const int w    = tid >> 5;
    const int l    = tid & 31;
    const int half = blockIdx.x & 1;
    const int lr   = l >> 2;             // 0..7
    const int kb   = (l & 3) * 2;        // 0,2,4,6
    const int rxor = lr << 4;            // per-thread swizzle constant

    // ---- one-time prologue: stage this half's e-splits (swizzled) + e2 ----
    {
        const uint4* s0 = (const uint4*)(g_b0 + half * KHALF * DDIM);
        const uint4* s1 = (const uint4*)(g_b1 + half * KHALF * DDIM);
        #pragma unroll
        for (int c = tid; c < KHALF * DDIM / 8; c += TPB) {   // 2048 x 16B
            const int row = c >> 3, cc = c & 7;
            const uint32_t off = SWZ(row * 128 + cc * 16);
            *(uint4*)(smem + SM_B0 + off) = s0[c];
            *(uint4*)(smem + SM_B1 + off) = s1[c];
        }
        #pragma unroll
        for (int i = tid; i < KHALF; i += TPB)
            ((float*)(smem + SM_E2))[i] = g_e2[half * KHALF + i];
    }

    const int   mrow0 = w * 16;          // 8 warps x 16 rows
    const float* z2s  = (const float*)(smem + SM_Z2);
    const float* e2s  = (const float*)(smem + SM_E2);

    // ---- persistent tile loop ----
    for (int tile = blockIdx.x >> 1; tile < NTILES; tile += 148) {
        __syncthreads();   // protect A-splits / z2 reuse

        // threads 0..127: own one z row — stream from global, compute z2
        // in the EXACT passing order, emit fp16 splits (scaled 2^3) swizzled.
        if (tid < MT) {
            const float4* zr = (const float4*)(z + ((size_t)tile * MT + tid) * DDIM);
            const int txor = (tid & 7) << 4;
            char* a0 = smem + SM_A0 + tid * 128;
            char* a1 = smem + SM_A1 + tid * 128;
            float c[8] = {0.f, 0.f, 0.f, 0.f, 0.f, 0.f, 0.f, 0.f};
            #pragma unroll
            for (int q = 0; q < 16; q++) {
                const float4 v = zr[q];
                // z2 partials: element e=4q+i updates c[e&7], j ascending
                c[(4 * q + 0) & 7] = fmaf(v.x, v.x, c[(4 * q + 0) & 7]);
                c[(4 * q + 1) & 7] = fmaf(v.y, v.y, c[(4 * q + 1) & 7]);
                c[(4 * q + 2) & 7] = fmaf(v.z, v.z, c[(4 * q + 2) & 7]);
                c[(4 * q + 3) & 7] = fmaf(v.w, v.w, c[(4 * q + 3) & 7]);
                // splits for cols 4q..4q+3 (two half2 stores each)
                const float sx = v.x * 8.0f, sy = v.y * 8.0f;
                const float sz = v.z * 8.0f, sw = v.w * 8.0f;
                const __half hx0 = __float2half_rn(sx);
                const __half hy0 = __float2half_rn(sy);
                const __half hz0 = __float2half_rn(sz);
                const __half hw0 = __float2half_rn(sw);
                const __half hx1 = __float2half_rn(sx - __half2float(hx0));
                const __half hy1 = __float2half_rn(sy - __half2float(hy0));
                const __half hz1 = __float2half_rn(sz - __half2float(hz0));
                const __half hw1 = __float2half_rn(sw - __half2float(hw0));
                const uint32_t o0 = (uint32_t)(8 * q) ^ txor;
                const uint32_t o1 = (uint32_t)(8 * q + 4) ^ txor;
                *(__half2*)(a0 + o0) = __halves2half2(hx0, hy0);
                *(__half2*)(a0 + o1) = __halves2half2(hz0, hw0);
                *(__half2*)(a1 + o0) = __halves2half2(hx1, hy1);
                *(__half2*)(a1 + o1) = __halves2half2(hz1, hw1);
            }
            const float lo = __fadd_rn(__fadd_rn(c[0], c[2]), __fadd_rn(c[4], c[6]));
            const float hi = __fadd_rn(__fadd_rn(c[1], c[3]), __fadd_rn(c[5], c[7]));
            ((float*)(smem + SM_Z2))[tid] = __fadd_rn(lo, hi);
        }
        __syncthreads();

        // A fragments in regs: [split][ktile][4]  (rows mrow0+lr, +8)
        uint32_t Af[2][4][4];
        {
            const char* A0 = smem + SM_A0;
            const char* A1 = smem + SM_A1;
            const int ro0 = (mrow0 + lr) * 128;
            const int ro1 = (mrow0 + lr + 8) * 128;
            #pragma unroll
            for (int kt = 0; kt < 4; kt++) {
                const uint32_t c0 = (uint32_t)((kt * 16 + kb) * 2) ^ rxor;
                const uint32_t c1 = (uint32_t)((kt * 16 + kb + 8) * 2) ^ rxor;
                Af[0][kt][0] = *(const uint32_t*)(A0 + ro0 + c0);
                Af[0][kt][1] = *(const uint32_t*)(A0 + ro1 + c0);
                Af[0][kt][2] = *(const uint32_t*)(A0 + ro0 + c1);
                Af[0][kt][3] = *(const uint32_t*)(A0 + ro1 + c1);
                Af[1][kt][0] = *(const uint32_t*)(A1 + ro0 + c0);
                Af[1][kt][1] = *(const uint32_t*)(A1 + ro1 + c0);
                Af[1][kt][2] = *(const uint32_t*)(A1 + ro0 + c1);
                Af[1][kt][3] = *(const uint32_t*)(A1 + ro1 + c1);
            }
        }

        const float z2a = z2s[mrow0 + lr];
        const float z2b = z2s[mrow0 + lr + 8];

        float bv[2] = {3.4e38f, 3.4e38f};
        int   bi[2] = {0, 0};

        // B-fragment loader (rows j*8+lr; swizzle = rxor)
        auto loadB = [&](uint32_t (&Bf)[2][4][2], int j) {
            const int ro = (j * 8 + lr) * 128;
            const char* B0 = smem + SM_B0;
            const char* B1 = smem + SM_B1;
            #pragma unroll
            for (int kt = 0; kt < 4; kt++) {
                const uint32_t c0 = (uint32_t)((kt * 16 + kb) * 2) ^ rxor;
                const uint32_t c1 = (uint32_t)((kt * 16 + kb + 8) * 2) ^ rxor;
                Bf[0][kt][0] = *(const uint32_t*)(B0 + ro + c0);
                Bf[0][kt][1] = *(const uint32_t*)(B0 + ro + c1);
                Bf[1][kt][0] = *(const uint32_t*)(B1 + ro + c0);
                Bf[1][kt][1] = *(const uint32_t*)(B1 + ro + c1);
            }
        };

        uint32_t Bbuf[2][2][4][2];
        loadB(Bbuf[0], 0);

        // ---- main loop: 32 n-tiles over this half, double-buffered B ----
        #pragma unroll 2
        for (int j = 0; j < 32; j++) {
            const int cur = j & 1;
            if (j < 31) loadB(Bbuf[cur ^ 1], j + 1);

            float C01[4] = {0.f, 0.f, 0.f, 0.f};   // a0*b1
            float C10[4] = {0.f, 0.f, 0.f, 0.f};   // a1*b0
            float C00[4] = {0.f, 0.f, 0.f, 0.f};   // a0*b0
            #pragma unroll
            for (int kt = 0; kt < 4; kt++) {
                mma16816(C01, Af[0][kt], Bbuf[cur][1][kt]);
                mma16816(C10, Af[1][kt], Bbuf[cur][0][kt]);
                mma16816(C00, Af[0][kt], Bbuf[cur][0][kt]);
            }

            const int ca = j * 8 + kb;
            const float e2a = e2s[ca], e2b = e2s[ca + 1];
            float td[4];
            #pragma unroll
            for (int q = 0; q < 4; q++) {
                const float s = __fadd_rn(__fadd_rn(C01[q], C10[q]), C00[q]);
                td[q] = __fmul_rn(s, TWO_DOT_SCALE);
            }
            const float d00 = __fadd_rn(__fsub_rn(z2a, td[0]), e2a);
            const float d01 = __fadd_rn(__fsub_rn(z2a, td[1]), e2b);
            const float d10 = __fadd_rn(__fsub_rn(z2b, td[2]), e2a);
            const float d11 = __fadd_rn(__fsub_rn(z2b, td[3]), e2b);
            if (d00 < bv[0]) { bv[0] = d00; bi[0] = ca; }
            if (d01 < bv[0]) { bv[0] = d01; bi[0] = ca + 1; }
            if (d10 < bv[1]) { bv[1] = d10; bi[1] = ca; }
            if (d11 < bv[1]) { bv[1] = d11; bi[1] = ca + 1; }
        }

        // quad reduce (min, lowest index on tie), write partials to global
        #pragma unroll
        for (int h = 0; h < 2; h++) {
            float v = bv[h];
            int   i = bi[h];
            #pragma unroll
            for (int s = 1; s <= 2; s <<= 1) {
                const float ov = __shfl_xor_sync(0xFFFFFFFFu, v, s);
                const int   oi = __shfl_xor_sync(0xFFFFFFFFu, i, s);
                if (ov < v || (ov == v && oi < i)) { v = ov; i = oi; }
            }
            if ((l & 3) == 0) {
                const int row = mrow0 + lr + h * 8;
                g_part[half][(size_t)tile * MT + row] =
                    make_float2(v, (float)(half * KHALF + i));
            }
        }
    }
}

// ---------------- merge halves, gather codes, write outputs ----------------
#define B_ROWS_PER_CTA 16
#define GRID_B (NROWS / B_ROWS_PER_CTA)   // 8192

__global__ __launch_bounds__(TPB, 8)
void vq_merge_gather_kernel(const float* __restrict__ emb,
                            float* __restrict__ out,
                            long long out_size) {
    __shared__ int sidx[B_ROWS_PER_CTA];

    const int tid  = threadIdx.x;
    const int rloc = tid >> 4;
    const int q    = tid & 15;
    const long long row0 = (long long)blockIdx.x * B_ROWS_PER_CTA;

    if (tid < B_ROWS_PER_CTA) {
        const long long n = row0 + tid;
        const float2 p0 = g_part[0][n];
        const float2 p1 = g_part[1][n];
        sidx[tid] = (p1.x < p0.x) ? (int)p1.y : (int)p0.y;  // half0 wins ties
    }
    __syncthreads();

    const long long n   = row0 + rloc;
    const int idx       = sidx[rloc];
    const float4 v      = ((const float4*)(emb + (long long)idx * DDIM))[q];
    const long long ND  = (long long)NROWS * DDIM;
    const long long off = n * DDIM + q * 4;

    if (out_size >= ND)      *((float4*)(out + off))      = v;  // z_q_st
    if (out_size >= 2 * ND)  *((float4*)(out + ND + off)) = v;  // z_q

    if (q == 0) {   // indices as float (0..511 exact)
        if (out_size >= 2 * ND + NROWS)      out[2 * ND + n] = (float)idx;
        else if (out_size == ND + NROWS)     out[ND + n]     = (float)idx;
        else if (out_size == NROWS)          out[n]          = (float)idx;
    }
}

// ---------------------------------------------------------------------------
extern "C" void kernel_launch(void* const* d_in, const int* in_sizes, int n_in,
                              void* d_out, int out_size) {
    const float* z   = (const float*)d_in[0];
    const float* emb = (const float*)d_in[1];
    if (n_in >= 2 && in_sizes[0] == KCB * DDIM && in_sizes[1] == NROWS * DDIM) {
        z   = (const float*)d_in[1];
        emb = (const float*)d_in[0];
    }

    static int configured = -1;
    if (configured < 0) {
        cudaFuncSetAttribute(vq_main_kernel,
                             cudaFuncAttributeMaxDynamicSharedMemorySize, SM_TOTAL);
        configured = 1;
    }

    vq_prep_kernel<<<4, 128>>>(emb);
    vq_main_kernel<<<GRID_MAIN, TPB, SM_TOTAL>>>(z);
    vq_merge_gather_kernel<<<GRID_B, TPB>>>(emb, (float*)d_out,
                                            (long long)out_size);
}